// round 13
// baseline (speedup 1.0000x reference)
#include <cuda_runtime.h>
#include <cuda_fp16.h>
#include <cstdint>

// ============================ helpers ============================
__device__ __forceinline__ uint32_t smem_to_u32(const void* smem_ptr) {
    uint32_t addr;
    asm("{ .reg .u64 tmp; cvta.to.shared.u64 tmp, %1; cvt.u32.u64 %0, tmp; }"
        : "=r"(addr) : "l"(smem_ptr));
    return addr;
}

#define CP_ASYNC16(dst, src) \
    asm volatile("cp.async.cg.shared.global [%0], [%1], 16;" \
                 :: "r"(dst), "l"(src) : "memory")
#define CP_COMMIT() asm volatile("cp.async.commit_group;" ::: "memory")
#define CP_WAIT_ALL() asm volatile("cp.async.wait_group 0;" ::: "memory")

__device__ __forceinline__ void ldmat_x4(uint32_t* r, uint32_t addr) {
    asm volatile("ldmatrix.sync.aligned.m8n8.x4.shared.b16 {%0,%1,%2,%3}, [%4];"
                 : "=r"(r[0]), "=r"(r[1]), "=r"(r[2]), "=r"(r[3]) : "r"(addr));
}
__device__ __forceinline__ void ldmat_x4_t(uint32_t* r, uint32_t addr) {
    asm volatile("ldmatrix.sync.aligned.m8n8.x4.trans.shared.b16 {%0,%1,%2,%3}, [%4];"
                 : "=r"(r[0]), "=r"(r[1]), "=r"(r[2]), "=r"(r[3]) : "r"(addr));
}
// fp16 inputs, fp32 accumulate
__device__ __forceinline__ void mma16816h(float* c, const uint32_t* a,
                                          uint32_t b0, uint32_t b1) {
    asm volatile(
        "mma.sync.aligned.m16n8k16.row.col.f32.f16.f16.f32 "
        "{%0,%1,%2,%3}, {%4,%5,%6,%7}, {%8,%9}, {%0,%1,%2,%3};"
        : "+f"(c[0]), "+f"(c[1]), "+f"(c[2]), "+f"(c[3])
        : "r"(a[0]), "r"(a[1]), "r"(a[2]), "r"(a[3]), "r"(b0), "r"(b1));
}

// ============================ scratch globals ============================
// Pre-split, pre-shifted fp16 planes of the blurred input.
// Layout: [b][py][pvar][ic][row 0..64][col 0..63], row pitch 64 fp16 = 128B.
//   pvar 0: px=1, col c holds x(ix=2c-1); pvar 1: px=1, col c holds x(ix=2c+1);
//   pvar 2: px=0, col c holds x(ix=2c).
// Row 0 of py=1 planes (iy=-1 border) is read but NEVER written: stays zero
// from static initialization across all launches/replays.
#define PL_SIZE 4160  // 65*64
__device__ __half g_ph[8L * 2 * 3 * 256 * PL_SIZE];  // hi, ~102 MB
__device__ __half g_pl[8L * 2 * 3 * 256 * PL_SIZE];  // lo, ~102 MB
__device__ float g_style[8 * 256];
__device__ float g_partial[4096];
__device__ float g_alpha[8 * 256];
// per-batch scaled weights (fp16 hi only), reordered k = t*256+ic
__device__ __align__(256) __half g_wA[8L * 256 * 2304];  // ~9.4 MB

#define LRELU_SLOPE 0.2f
#define SQRT2F 1.41421356237309515f

// ============================ K1: blur + split + style ============================
// blocks [0,4096): blur one half-plane, write fp16 hi/lo parity-variant planes
//                  + sum-of-squares partial.
// blocks [4096,4352): style[b,i] = s[b,:]@style_w[i,:] + style_b[i] (one warp per (b,i))
#define BLUR_IN_W 136
#define BLUR_SMEM ((68 * BLUR_IN_W + 68 * 128 + 8) * 4)

__global__ __launch_bounds__(256) void blur_kernel(const float* __restrict__ x,
                                                   const float* __restrict__ s,
                                                   const float* __restrict__ style_w,
                                                   const float* __restrict__ style_b) {
    if (blockIdx.x >= 4096) {
        int wg = (blockIdx.x - 4096) * 8 + (threadIdx.x >> 5);  // b*256+i
        int lane = threadIdx.x & 31;
        int b = wg >> 8, i = wg & 255;
        const float* sp = s + b * 512;
        const float* wp = style_w + i * 512;
        float acc = 0.f;
#pragma unroll 4
        for (int j = lane; j < 512; j += 32) acc += sp[j] * wp[j];
#pragma unroll
        for (int o = 16; o; o >>= 1) acc += __shfl_xor_sync(0xffffffffu, acc, o);
        if (lane == 0) g_style[wg] = acc + style_b[i];
        return;
    }

    extern __shared__ __align__(16) float sm[];
    float* in = sm;                     // [68][136], data at cols 4..131
    float* hb = sm + 68 * BLUR_IN_W;    // [68][128]
    float* red = hb + 68 * 128;

    const int bat = blockIdx.x >> 9;
    const int inBlk = blockIdx.x & 511;
    const int c = inBlk >> 1;
    const int plane = bat * 256 + c;
    const int h0 = (inBlk & 1) * 64;
    const int tid = threadIdx.x;
    const float* xp = x + (long)plane * 16384;

    for (int t = tid; t < 544; t += 256) {
        int r = t >> 3, j = t & 7;
        in[r * BLUR_IN_W + (j < 4 ? j : 128 + j)] = 0.f;
    }
    for (int pos = tid; pos < 68 * 32; pos += 256) {
        int r = pos >> 5, c4 = pos & 31;
        int h = h0 - 2 + r;
        float4 v = make_float4(0.f, 0.f, 0.f, 0.f);
        if ((unsigned)h < 128u)
            v = *reinterpret_cast<const float4*>(xp + h * 128 + c4 * 4);
        *reinterpret_cast<float4*>(in + r * BLUR_IN_W + 4 + c4 * 4) = v;
    }
    __syncthreads();

    for (int pos = tid; pos < 68 * 32; pos += 256) {
        int r = pos >> 5, c4 = pos & 31;
        const float* row = in + r * BLUR_IN_W + c4 * 4;
        float4 a = *reinterpret_cast<const float4*>(row);
        float4 bb = *reinterpret_cast<const float4*>(row + 4);
        float4 cc = *reinterpret_cast<const float4*>(row + 8);
        float4 o;
        o.x = a.z + 4.f * a.w + 6.f * bb.x + 4.f * bb.y + bb.z;
        o.y = a.w + 4.f * bb.x + 6.f * bb.y + 4.f * bb.z + bb.w;
        o.z = bb.x + 4.f * bb.y + 6.f * bb.z + 4.f * bb.w + cc.x;
        o.w = bb.y + 4.f * bb.z + 6.f * bb.w + 4.f * cc.x + cc.y;
        *reinterpret_cast<float4*>(hb + r * 128 + c4 * 4) = o;
    }
    __syncthreads();

    float ss = 0.f;
    for (int pos = tid; pos < 64 * 32; pos += 256) {
        int r = pos >> 5, c4 = pos & 31;  // c4 == lane (stride 256)
        const float* col = hb + r * 128 + c4 * 4;
        float4 h0v = *reinterpret_cast<const float4*>(col);
        float4 h1v = *reinterpret_cast<const float4*>(col + 128);
        float4 h2v = *reinterpret_cast<const float4*>(col + 256);
        float4 h3v = *reinterpret_cast<const float4*>(col + 384);
        float4 h4v = *reinterpret_cast<const float4*>(col + 512);
        // v0..v3 at ix = 4*c4 + {0,1,2,3}, iy = h0 + r
        float v0 = (h0v.x + 4.f * h1v.x + 6.f * h2v.x + 4.f * h3v.x + h4v.x) * (1.f / 256.f);
        float v1 = (h0v.y + 4.f * h1v.y + 6.f * h2v.y + 4.f * h3v.y + h4v.y) * (1.f / 256.f);
        float v2 = (h0v.z + 4.f * h1v.z + 6.f * h2v.z + 4.f * h3v.z + h4v.z) * (1.f / 256.f);
        float v3 = (h0v.w + 4.f * h1v.w + 6.f * h2v.w + 4.f * h3v.w + h4v.w) * (1.f / 256.f);
        ss += v0 * v0 + v1 * v1 + v2 * v2 + v3 * v3;

        unsigned short hh[4]; unsigned short ll[4];
#pragma unroll
        for (int j = 0; j < 4; j++) {
            float v = (j == 0) ? v0 : (j == 1) ? v1 : (j == 2) ? v2 : v3;
            __half hv = __float2half(v);
            __half lv = __float2half(v - __half2float(hv));
            hh[j] = __half_as_ushort(hv);
            ll[j] = __half_as_ushort(lv);
        }
        // neighbor v3 (ix = 4c4-1) for the pvar0 packed write
        unsigned ph3 = __shfl_up_sync(0xffffffffu, (unsigned)hh[3], 1);
        unsigned pl3 = __shfl_up_sync(0xffffffffu, (unsigned)ll[3], 1);
        if (c4 == 0) { ph3 = 0u; pl3 = 0u; }  // x(-1) = 0 border

        int iy = h0 + r;
        int py = iy & 1;
        int prow = (iy >> 1) + 1;
        long rowOff = (long)prow * 64;
        long p0b = ((long)((bat * 2 + py) * 3 + 0) * 256 + c) * PL_SIZE + rowOff;
        long p1b = ((long)((bat * 2 + py) * 3 + 1) * 256 + c) * PL_SIZE + rowOff;
        long p2b = ((long)((bat * 2 + py) * 3 + 2) * 256 + c) * PL_SIZE + rowOff;
        int col2 = 2 * c4;

        // pvar2 (px=0): (v0, v2)
        *reinterpret_cast<unsigned*>(&g_ph[p2b + col2]) = (unsigned)hh[0] | ((unsigned)hh[2] << 16);
        *reinterpret_cast<unsigned*>(&g_pl[p2b + col2]) = (unsigned)ll[0] | ((unsigned)ll[2] << 16);
        // pvar1 (x(2c+1)): (v1, v3)
        *reinterpret_cast<unsigned*>(&g_ph[p1b + col2]) = (unsigned)hh[1] | ((unsigned)hh[3] << 16);
        *reinterpret_cast<unsigned*>(&g_pl[p1b + col2]) = (unsigned)ll[1] | ((unsigned)ll[3] << 16);
        // pvar0 (x(2c-1)): (prev v3, v1)
        *reinterpret_cast<unsigned*>(&g_ph[p0b + col2]) = ph3 | ((unsigned)hh[1] << 16);
        *reinterpret_cast<unsigned*>(&g_pl[p0b + col2]) = pl3 | ((unsigned)ll[1] << 16);
    }
#pragma unroll
    for (int o = 16; o; o >>= 1) ss += __shfl_xor_sync(0xffffffffu, ss, o);
    if ((tid & 31) == 0) red[tid >> 5] = ss;
    __syncthreads();
    if (tid == 0) {
        float t = 0.f;
#pragma unroll
        for (int k = 0; k < 8; k++) t += red[k];
        g_partial[bat * 512 + inBlk] = t;
    }
}

// ============================ K2: wsplit + rscale + alpha ============================
__global__ __launch_bounds__(256) void wsplit_kernel(const float* __restrict__ w,
                                                     const float* __restrict__ norm_g) {
    __shared__ float ws[2304];
    __shared__ float rs[256];
    __shared__ float red[8];
    const int o = blockIdx.x;
    const int bat = blockIdx.y;
    const int tid = threadIdx.x;

    const float4* wsrc = reinterpret_cast<const float4*>(w + (long)o * 2304);
    for (int i = tid; i < 576; i += 256)
        *reinterpret_cast<float4*>(ws + i * 4) = wsrc[i];

    {
        int p = bat * 256 + tid;
        float ssum = g_partial[2 * p] + g_partial[2 * p + 1];
        float ms = ssum * (1.f / 16384.f);
        rs[tid] = rsqrtf(ms + 1e-8f) * norm_g[tid] * g_style[p];
    }
    __syncthreads();

    {
        float sv = g_style[bat * 256 + tid];
        float wq = 0.f;
#pragma unroll
        for (int t = 0; t < 9; t++) { float v = ws[tid * 9 + t]; wq += v * v; }
        float pa = sv * sv * wq;
#pragma unroll
        for (int off = 16; off; off >>= 1) pa += __shfl_xor_sync(0xffffffffu, pa, off);
        if ((tid & 31) == 0) red[tid >> 5] = pa;
    }

    {
        const float rsc = rs[tid];
        long dstBase = (long)(bat * 256 + o) * 2304 + tid;
#pragma unroll
        for (int t = 0; t < 9; t++)
            g_wA[dstBase + t * 256] = __float2half(ws[tid * 9 + t] * rsc);
    }

    __syncthreads();
    if (tid == 0) {
        float acc = 0.f;
#pragma unroll
        for (int k = 0; k < 8; k++) acc += red[k];
        const float sc = 1.f / 48.f;  // 1/sqrt(256*9)
        g_alpha[bat * 256 + o] = sc * rsqrtf(sc * sc * acc + 1e-8f);
    }
}

// ============================ K3: HMMA conv GEMM ============================
// CTA tile: M=128 (o), N=64 (one output row). grid (64,2,8).
// K = 2304 = 36 chunks of 64. fp16 2-term: C = Ah*Bh + Ah*Bl (Al dropped, ~2e-4).
// ALL staging via cp.async.cg 16B. smem: A 16KB + B hi/lo 8+8KB per stage,
// double-buffered = 64KB -> 3 CTAs/SM.

#define SA(st)   ((st) * 16384)
#define SB_H(st) (32768 + (st) * 8192)
#define SB_L(st) (49152 + (st) * 8192)
#define CONV_SMEM 65536

__global__ __launch_bounds__(256, 3)
void mma_conv_kernel(const float* __restrict__ cbias, float* __restrict__ out) {
    extern __shared__ __align__(1024) char smem[];
    const uint32_t sb = smem_to_u32(smem);
    const int tid = threadIdx.x;
    const int lane = tid & 31;
    const int wid = tid >> 5;
    const int warpM = wid >> 1;         // 0..3 (32 rows each)
    const int warpN = wid & 1;          // 0..1 (32 cols each)
    const int bat = blockIdx.z;
    const int mBase = blockIdx.y * 128;
    const int oy = blockIdx.x;          // output row
    const int nBase = blockIdx.x * 64;

    // ---- A staging: 8 lanes per 128B row-line, 4 rows per thread ----
    const int aj = tid & 7;
    const int ar0 = tid >> 3;           // 0..31

    // ---- B staging: 4 threads per ic-row, 2 units each ----
    const int icB = tid >> 2;           // 0..63
    const int u0 = (tid & 3) * 2;       // 0,2,4,6
    const int bsw0 = icB * 128 + (((u0    ) ^ (icB & 7)) & 7) * 16;
    const int bsw1 = icB * 128 + (((u0 + 1) ^ (icB & 7)) & 7) * 16;

    // ---- fragment constants ----
    const int laneRow = lane & 15;
    const int laneSel = lane >> 4;
    const int mW = warpM * 32;
    const int nW = warpN * 32;
    int mRowB[2], mRow7[2];
#pragma unroll
    for (int mt = 0; mt < 2; mt++) {
        int m = mW + mt * 16 + laneRow;
        mRowB[mt] = m * 128;
        mRow7[mt] = m & 7;
    }
    const int bKRow = laneRow * 128;
    const int bK7 = laneRow & 7;
    int bUn[2];
#pragma unroll
    for (int nt2 = 0; nt2 < 2; nt2++)
        bUn[nt2] = warpN * 4 + nt2 * 2 + laneSel;   // 0..7

    float acc[2][4][4];
#pragma unroll
    for (int i = 0; i < 2; i++)
#pragma unroll
        for (int j = 0; j < 4; j++)
#pragma unroll
            for (int k = 0; k < 4; k++) acc[i][j][k] = 0.f;

    auto issueA = [&](int stage, int chunk) {
#pragma unroll
        for (int p = 0; p < 4; p++) {
            int r = ar0 + 32 * p;
            long src = (long)(bat * 256 + mBase + r) * 2304 + chunk * 64 + aj * 8;
            int sw = r * 128 + ((aj ^ (r & 7)) & 7) * 16;
            CP_ASYNC16(sb + SA(stage) + sw, g_wA + src);
        }
    };
    auto issueB = [&](int stage, int chunk) {
        int tap = chunk >> 2;
        int icq = chunk & 3;
        int ty = (tap >= 6) ? 2 : (tap >= 3 ? 1 : 0);
        int tx = tap - ty * 3;
        int py = (ty == 1) ? 0 : 1;
        int pvar = (tx == 0) ? 0 : (tx == 2 ? 1 : 2);
        int row = oy + (ty != 0);
        long base = ((long)((bat * 2 + py) * 3 + pvar) * 256 + icq * 64 + icB)
                    * (long)PL_SIZE + (long)row * 64;
        CP_ASYNC16(sb + SB_H(stage) + bsw0, g_ph + base + u0 * 8);
        CP_ASYNC16(sb + SB_H(stage) + bsw1, g_ph + base + (u0 + 1) * 8);
        CP_ASYNC16(sb + SB_L(stage) + bsw0, g_pl + base + u0 * 8);
        CP_ASYNC16(sb + SB_L(stage) + bsw1, g_pl + base + (u0 + 1) * 8);
    };

    // ===== prologue: fill stage 0 =====
    issueA(0, 0);
    issueB(0, 0);
    CP_COMMIT();
    CP_WAIT_ALL();
    __syncthreads();

    // ===== mainloop =====
    for (int chunk = 0; chunk < 36; ++chunk) {
        const int cur = chunk & 1;
        const int nxt = cur ^ 1;
        const bool hasNext = (chunk + 1 < 36);
        if (hasNext) {
            issueA(nxt, chunk + 1);
            issueB(nxt, chunk + 1);
            CP_COMMIT();
        }

        const uint32_t aBase  = sb + SA(cur);
        const uint32_t bHBase = sb + SB_H(cur);
        const uint32_t bLBase = sb + SB_L(cur);

#pragma unroll
        for (int kk = 0; kk < 4; kk++) {
            uint32_t aH[2][4], bH[2][4], bL[2][4];
#pragma unroll
            for (int mt = 0; mt < 2; mt++) {
                int u = kk * 2 + laneSel;
                int off = mRowB[mt] + ((u ^ mRow7[mt]) & 7) * 16;
                ldmat_x4(aH[mt], aBase + off);
            }
#pragma unroll
            for (int nt2 = 0; nt2 < 2; nt2++) {
                int off = kk * 16 * 128 + bKRow + ((bUn[nt2] ^ bK7) & 7) * 16;
                ldmat_x4_t(bH[nt2], bHBase + off);
                ldmat_x4_t(bL[nt2], bLBase + off);
            }
#pragma unroll
            for (int mt = 0; mt < 2; mt++) {
#pragma unroll
                for (int nt = 0; nt < 4; nt++) {
                    int nt2 = nt >> 1, sub = (nt & 1) * 2;
                    mma16816h(acc[mt][nt], aH[mt], bH[nt2][sub], bH[nt2][sub + 1]);
                    mma16816h(acc[mt][nt], aH[mt], bL[nt2][sub], bL[nt2][sub + 1]);
                }
            }
        }

        CP_WAIT_ALL();
        __syncthreads();
    }

    // ===== epilogue: alpha, bias, scaled LeakyReLU =====
    const int rowInTile = lane >> 2;
    const int colInTile = (lane & 3) * 2;
#pragma unroll
    for (int mt = 0; mt < 2; mt++) {
        int o0 = mBase + mW + mt * 16 + rowInTile;
        int o1 = o0 + 8;
        float al0 = g_alpha[bat * 256 + o0], bi0 = cbias[o0];
        float al1 = g_alpha[bat * 256 + o1], bi1 = cbias[o1];
        float* p0 = out + (long)(bat * 256 + o0) * 4096 + nBase + nW + colInTile;
        float* p1 = out + (long)(bat * 256 + o1) * 4096 + nBase + nW + colInTile;
#pragma unroll
        for (int nt = 0; nt < 4; nt++) {
            float2 v0, v1;
            float v;
            v = acc[mt][nt][0] * al0 + bi0;
            v0.x = (v >= 0.f ? v : LRELU_SLOPE * v) * SQRT2F;
            v = acc[mt][nt][1] * al0 + bi0;
            v0.y = (v >= 0.f ? v : LRELU_SLOPE * v) * SQRT2F;
            v = acc[mt][nt][2] * al1 + bi1;
            v1.x = (v >= 0.f ? v : LRELU_SLOPE * v) * SQRT2F;
            v = acc[mt][nt][3] * al1 + bi1;
            v1.y = (v >= 0.f ? v : LRELU_SLOPE * v) * SQRT2F;
            *reinterpret_cast<float2*>(p0 + nt * 8) = v0;
            *reinterpret_cast<float2*>(p1 + nt * 8) = v1;
        }
    }
}

// ============================ launch ============================
extern "C" void kernel_launch(void* const* d_in, const int* in_sizes, int n_in,
                              void* d_out, int out_size) {
    const float* x       = (const float*)d_in[0];  // [8,256,128,128]
    const float* s       = (const float*)d_in[1];  // [8,512]
    const float* conv_w  = (const float*)d_in[2];  // [256,256,3,3]
    const float* conv_b  = (const float*)d_in[3];  // [256]
    const float* style_w = (const float*)d_in[4];  // [256,512]
    const float* style_b = (const float*)d_in[5];  // [256]
    const float* norm_g  = (const float*)d_in[6];  // [256]
    float* out = (float*)d_out;                    // [8,256,64,64]

    static int inited = 0;
    if (!inited) {
        cudaFuncSetAttribute(mma_conv_kernel,
                             cudaFuncAttributeMaxDynamicSharedMemorySize, CONV_SMEM);
        cudaFuncSetAttribute(blur_kernel,
                             cudaFuncAttributeMaxDynamicSharedMemorySize, BLUR_SMEM);
        inited = 1;
    }

    blur_kernel<<<4352, 256, BLUR_SMEM>>>(x, s, style_w, style_b);     // launch 1
    wsplit_kernel<<<dim3(256, 8), 256>>>(conv_w, norm_g);              // launch 2
    mma_conv_kernel<<<dim3(64, 2, 8), 256, CONV_SMEM>>>(conv_b, out);  // launch 3
}

// round 16
// speedup vs baseline: 1.5697x; 1.5697x over previous
#include <cuda_runtime.h>
#include <cuda_fp16.h>
#include <cstdint>

// ============================ helpers ============================
__device__ __forceinline__ uint32_t smem_to_u32(const void* smem_ptr) {
    uint32_t addr;
    asm("{ .reg .u64 tmp; cvta.to.shared.u64 tmp, %1; cvt.u32.u64 %0, tmp; }"
        : "=r"(addr) : "l"(smem_ptr));
    return addr;
}

#define CP_ASYNC16(dst, src) \
    asm volatile("cp.async.cg.shared.global [%0], [%1], 16;" \
                 :: "r"(dst), "l"(src) : "memory")
#define CP_COMMIT() asm volatile("cp.async.commit_group;" ::: "memory")
#define CP_WAIT_ALL() asm volatile("cp.async.wait_group 0;" ::: "memory")

__device__ __forceinline__ void ldmat_x4(uint32_t* r, uint32_t addr) {
    asm volatile("ldmatrix.sync.aligned.m8n8.x4.shared.b16 {%0,%1,%2,%3}, [%4];"
                 : "=r"(r[0]), "=r"(r[1]), "=r"(r[2]), "=r"(r[3]) : "r"(addr));
}
__device__ __forceinline__ void ldmat_x4_t(uint32_t* r, uint32_t addr) {
    asm volatile("ldmatrix.sync.aligned.m8n8.x4.trans.shared.b16 {%0,%1,%2,%3}, [%4];"
                 : "=r"(r[0]), "=r"(r[1]), "=r"(r[2]), "=r"(r[3]) : "r"(addr));
}
// fp16 inputs, fp32 accumulate
__device__ __forceinline__ void mma16816h(float* c, const uint32_t* a,
                                          uint32_t b0, uint32_t b1) {
    asm volatile(
        "mma.sync.aligned.m16n8k16.row.col.f32.f16.f16.f32 "
        "{%0,%1,%2,%3}, {%4,%5,%6,%7}, {%8,%9}, {%0,%1,%2,%3};"
        : "+f"(c[0]), "+f"(c[1]), "+f"(c[2]), "+f"(c[3])
        : "r"(a[0]), "r"(a[1]), "r"(a[2]), "r"(a[3]), "r"(b0), "r"(b1));
}

// ============================ scratch globals ============================
// Pre-split, pre-shifted fp16 planes of the blurred input.
// Layout: [b][py][pvar][ic][row 0..64][col 0..63], row pitch 64 fp16 = 128B.
//   pvar 0: px=1, col c holds x(ix=2c-1); pvar 1: px=1, col c holds x(ix=2c+1);
//   pvar 2: px=0, col c holds x(ix=2c).
// Row 0 of py=1 planes (iy=-1 border) is read but NEVER written: stays zero
// from static initialization across all launches/replays.
#define PL_SIZE 4160  // 65*64
__device__ __half g_ph[8L * 2 * 3 * 256 * PL_SIZE];  // hi, ~102 MB
__device__ __half g_pl[8L * 2 * 3 * 256 * PL_SIZE];  // lo, ~102 MB
__device__ float g_style[8 * 256];
__device__ float g_partial[4096];
__device__ float g_alpha[8 * 256];
// per-batch scaled weights (fp16 hi only), reordered k = t*256+ic
__device__ __align__(256) __half g_wA[8L * 256 * 2304];  // ~9.4 MB

#define LRELU_SLOPE 0.2f
#define SQRT2F 1.41421356237309515f

// ============================ K1: blur + split + style ============================
// blocks [0,4096): blur one half-plane (horizontal via lane shuffles, vertical
//   via one smem buffer), write fp16 hi/lo parity-variant planes + sumsq partial.
// blocks [4096,4352): style[b,i] = s[b,:]@style_w[i,:] + style_b[i]
#define BLUR_SMEM ((68 * 128 + 8) * 4)   // 34.9 KB -> 6 CTAs/SM

__global__ __launch_bounds__(256) void blur_kernel(const float* __restrict__ x,
                                                   const float* __restrict__ s,
                                                   const float* __restrict__ style_w,
                                                   const float* __restrict__ style_b) {
    if (blockIdx.x >= 4096) {
        int wg = (blockIdx.x - 4096) * 8 + (threadIdx.x >> 5);  // b*256+i
        int lane = threadIdx.x & 31;
        int b = wg >> 8, i = wg & 255;
        const float* sp = s + b * 512;
        const float* wp = style_w + i * 512;
        float acc = 0.f;
#pragma unroll 4
        for (int j = lane; j < 512; j += 32) acc += sp[j] * wp[j];
#pragma unroll
        for (int o = 16; o; o >>= 1) acc += __shfl_xor_sync(0xffffffffu, acc, o);
        if (lane == 0) g_style[wg] = acc + style_b[i];
        return;
    }

    extern __shared__ __align__(16) float sm[];
    float* hb = sm;              // [68][128] horizontally-blurred rows
    float* red = hb + 68 * 128;

    const int bat = blockIdx.x >> 9;
    const int inBlk = blockIdx.x & 511;
    const int c = inBlk >> 1;
    const int plane = bat * 256 + c;
    const int h0 = (inBlk & 1) * 64;
    const int tid = threadIdx.x;
    const float* xp = x + (long)plane * 16384;

    // horizontal pass: direct global load + lane shuffles (c4 == lane)
    for (int pos = tid; pos < 68 * 32; pos += 256) {
        int r = pos >> 5, c4 = pos & 31;
        int h = h0 - 2 + r;
        float4 v = make_float4(0.f, 0.f, 0.f, 0.f);
        if ((unsigned)h < 128u)
            v = *reinterpret_cast<const float4*>(xp + h * 128 + c4 * 4);
        float lz = __shfl_up_sync(0xffffffffu, v.z, 1);
        float lw = __shfl_up_sync(0xffffffffu, v.w, 1);
        float rx = __shfl_down_sync(0xffffffffu, v.x, 1);
        float ry = __shfl_down_sync(0xffffffffu, v.y, 1);
        if (c4 == 0)  { lz = 0.f; lw = 0.f; }
        if (c4 == 31) { rx = 0.f; ry = 0.f; }
        float4 o;
        o.x = lz + 4.f * lw + 6.f * v.x + 4.f * v.y + v.z;
        o.y = lw + 4.f * v.x + 6.f * v.y + 4.f * v.z + v.w;
        o.z = v.x + 4.f * v.y + 6.f * v.z + 4.f * v.w + rx;
        o.w = v.y + 4.f * v.z + 6.f * v.w + 4.f * rx + ry;
        *reinterpret_cast<float4*>(hb + r * 128 + c4 * 4) = o;
    }
    __syncthreads();

    // vertical pass + fp16 hi/lo split + parity-variant writes + sumsq
    float ss = 0.f;
    for (int pos = tid; pos < 64 * 32; pos += 256) {
        int r = pos >> 5, c4 = pos & 31;  // c4 == lane
        const float* col = hb + r * 128 + c4 * 4;
        float4 h0v = *reinterpret_cast<const float4*>(col);
        float4 h1v = *reinterpret_cast<const float4*>(col + 128);
        float4 h2v = *reinterpret_cast<const float4*>(col + 256);
        float4 h3v = *reinterpret_cast<const float4*>(col + 384);
        float4 h4v = *reinterpret_cast<const float4*>(col + 512);
        // v0..v3 at ix = 4*c4 + {0,1,2,3}, iy = h0 + r
        float v0 = (h0v.x + 4.f * h1v.x + 6.f * h2v.x + 4.f * h3v.x + h4v.x) * (1.f / 256.f);
        float v1 = (h0v.y + 4.f * h1v.y + 6.f * h2v.y + 4.f * h3v.y + h4v.y) * (1.f / 256.f);
        float v2 = (h0v.z + 4.f * h1v.z + 6.f * h2v.z + 4.f * h3v.z + h4v.z) * (1.f / 256.f);
        float v3 = (h0v.w + 4.f * h1v.w + 6.f * h2v.w + 4.f * h3v.w + h4v.w) * (1.f / 256.f);
        ss += v0 * v0 + v1 * v1 + v2 * v2 + v3 * v3;

        unsigned short hh[4]; unsigned short ll[4];
#pragma unroll
        for (int j = 0; j < 4; j++) {
            float v = (j == 0) ? v0 : (j == 1) ? v1 : (j == 2) ? v2 : v3;
            __half hv = __float2half(v);
            __half lv = __float2half(v - __half2float(hv));
            hh[j] = __half_as_ushort(hv);
            ll[j] = __half_as_ushort(lv);
        }
        // neighbor v3 (ix = 4c4-1) for the pvar0 packed write
        unsigned ph3 = __shfl_up_sync(0xffffffffu, (unsigned)hh[3], 1);
        unsigned pl3 = __shfl_up_sync(0xffffffffu, (unsigned)ll[3], 1);
        if (c4 == 0) { ph3 = 0u; pl3 = 0u; }  // x(-1) = 0 border

        int iy = h0 + r;
        int py = iy & 1;
        int prow = (iy >> 1) + 1;
        long rowOff = (long)prow * 64;
        long p0b = ((long)((bat * 2 + py) * 3 + 0) * 256 + c) * PL_SIZE + rowOff;
        long p1b = ((long)((bat * 2 + py) * 3 + 1) * 256 + c) * PL_SIZE + rowOff;
        long p2b = ((long)((bat * 2 + py) * 3 + 2) * 256 + c) * PL_SIZE + rowOff;
        int col2 = 2 * c4;

        // pvar2 (px=0): (v0, v2)
        *reinterpret_cast<unsigned*>(&g_ph[p2b + col2]) = (unsigned)hh[0] | ((unsigned)hh[2] << 16);
        *reinterpret_cast<unsigned*>(&g_pl[p2b + col2]) = (unsigned)ll[0] | ((unsigned)ll[2] << 16);
        // pvar1 (x(2c+1)): (v1, v3)
        *reinterpret_cast<unsigned*>(&g_ph[p1b + col2]) = (unsigned)hh[1] | ((unsigned)hh[3] << 16);
        *reinterpret_cast<unsigned*>(&g_pl[p1b + col2]) = (unsigned)ll[1] | ((unsigned)ll[3] << 16);
        // pvar0 (x(2c-1)): (prev v3, v1)
        *reinterpret_cast<unsigned*>(&g_ph[p0b + col2]) = ph3 | ((unsigned)hh[1] << 16);
        *reinterpret_cast<unsigned*>(&g_pl[p0b + col2]) = pl3 | ((unsigned)ll[1] << 16);
    }
#pragma unroll
    for (int o = 16; o; o >>= 1) ss += __shfl_xor_sync(0xffffffffu, ss, o);
    if ((tid & 31) == 0) red[tid >> 5] = ss;
    __syncthreads();
    if (tid == 0) {
        float t = 0.f;
#pragma unroll
        for (int k = 0; k < 8; k++) t += red[k];
        g_partial[bat * 512 + inBlk] = t;
    }
}

// ============================ K2: wsplit + rscale + alpha ============================
__global__ __launch_bounds__(256) void wsplit_kernel(const float* __restrict__ w,
                                                     const float* __restrict__ norm_g) {
    __shared__ float ws[2304];
    __shared__ float rs[256];
    __shared__ float red[8];
    const int o = blockIdx.x;
    const int bat = blockIdx.y;
    const int tid = threadIdx.x;

    const float4* wsrc = reinterpret_cast<const float4*>(w + (long)o * 2304);
    for (int i = tid; i < 576; i += 256)
        *reinterpret_cast<float4*>(ws + i * 4) = wsrc[i];

    {
        int p = bat * 256 + tid;
        float ssum = g_partial[2 * p] + g_partial[2 * p + 1];
        float ms = ssum * (1.f / 16384.f);
        rs[tid] = rsqrtf(ms + 1e-8f) * norm_g[tid] * g_style[p];
    }
    __syncthreads();

    {
        float sv = g_style[bat * 256 + tid];
        float wq = 0.f;
#pragma unroll
        for (int t = 0; t < 9; t++) { float v = ws[tid * 9 + t]; wq += v * v; }
        float pa = sv * sv * wq;
#pragma unroll
        for (int off = 16; off; off >>= 1) pa += __shfl_xor_sync(0xffffffffu, pa, off);
        if ((tid & 31) == 0) red[tid >> 5] = pa;
    }

    {
        const float rsc = rs[tid];
        long dstBase = (long)(bat * 256 + o) * 2304 + tid;
#pragma unroll
        for (int t = 0; t < 9; t++)
            g_wA[dstBase + t * 256] = __float2half(ws[tid * 9 + t] * rsc);
    }

    __syncthreads();
    if (tid == 0) {
        float acc = 0.f;
#pragma unroll
        for (int k = 0; k < 8; k++) acc += red[k];
        const float sc = 1.f / 48.f;  // 1/sqrt(256*9)
        g_alpha[bat * 256 + o] = sc * rsqrtf(sc * sc * acc + 1e-8f);
    }
}

// ============================ K3: HMMA conv GEMM ============================
// CTA tile: M=128 (o), N=64 (one output row). grid (64,2,8).
// K = 2304 = 36 chunks of 64. fp16 2-term: C = Ah*Bh + Ah*Bl (Al dropped, ~2e-4).
// ALL staging via cp.async.cg 16B. smem: A 16KB + B hi/lo 8+8KB per stage,
// double-buffered = 64KB. launch_bounds(256,2): NO register cap -> no spills.

#define SA(st)   ((st) * 16384)
#define SB_H(st) (32768 + (st) * 8192)
#define SB_L(st) (49152 + (st) * 8192)
#define CONV_SMEM 65536

__global__ __launch_bounds__(256, 2)
void mma_conv_kernel(const float* __restrict__ cbias, float* __restrict__ out) {
    extern __shared__ __align__(1024) char smem[];
    const uint32_t sb = smem_to_u32(smem);
    const int tid = threadIdx.x;
    const int lane = tid & 31;
    const int wid = tid >> 5;
    const int warpM = wid >> 1;         // 0..3 (32 rows each)
    const int warpN = wid & 1;          // 0..1 (32 cols each)
    const int bat = blockIdx.z;
    const int mBase = blockIdx.y * 128;
    const int oy = blockIdx.x;          // output row
    const int nBase = blockIdx.x * 64;

    // ---- A staging: 8 lanes per 128B row-line, 4 rows per thread ----
    const int aj = tid & 7;
    const int ar0 = tid >> 3;           // 0..31

    // ---- B staging: 4 threads per ic-row, 2 units each ----
    const int icB = tid >> 2;           // 0..63
    const int u0 = (tid & 3) * 2;       // 0,2,4,6
    const int bsw0 = icB * 128 + (((u0    ) ^ (icB & 7)) & 7) * 16;
    const int bsw1 = icB * 128 + (((u0 + 1) ^ (icB & 7)) & 7) * 16;

    // ---- fragment constants ----
    const int laneRow = lane & 15;
    const int laneSel = lane >> 4;
    const int mW = warpM * 32;
    const int nW = warpN * 32;
    int mRowB[2], mRow7[2];
#pragma unroll
    for (int mt = 0; mt < 2; mt++) {
        int m = mW + mt * 16 + laneRow;
        mRowB[mt] = m * 128;
        mRow7[mt] = m & 7;
    }
    const int bKRow = laneRow * 128;
    const int bK7 = laneRow & 7;
    int bUn[2];
#pragma unroll
    for (int nt2 = 0; nt2 < 2; nt2++)
        bUn[nt2] = warpN * 4 + nt2 * 2 + laneSel;   // 0..7

    float acc[2][4][4];
#pragma unroll
    for (int i = 0; i < 2; i++)
#pragma unroll
        for (int j = 0; j < 4; j++)
#pragma unroll
            for (int k = 0; k < 4; k++) acc[i][j][k] = 0.f;

    auto issueA = [&](int stage, int chunk) {
#pragma unroll
        for (int p = 0; p < 4; p++) {
            int r = ar0 + 32 * p;
            long src = (long)(bat * 256 + mBase + r) * 2304 + chunk * 64 + aj * 8;
            int sw = r * 128 + ((aj ^ (r & 7)) & 7) * 16;
            CP_ASYNC16(sb + SA(stage) + sw, g_wA + src);
        }
    };
    auto issueB = [&](int stage, int chunk) {
        int tap = chunk >> 2;
        int icq = chunk & 3;
        int ty = (tap >= 6) ? 2 : (tap >= 3 ? 1 : 0);
        int tx = tap - ty * 3;
        int py = (ty == 1) ? 0 : 1;
        int pvar = (tx == 0) ? 0 : (tx == 2 ? 1 : 2);
        int row = oy + (ty != 0);
        long base = ((long)((bat * 2 + py) * 3 + pvar) * 256 + icq * 64 + icB)
                    * (long)PL_SIZE + (long)row * 64;
        CP_ASYNC16(sb + SB_H(stage) + bsw0, g_ph + base + u0 * 8);
        CP_ASYNC16(sb + SB_H(stage) + bsw1, g_ph + base + (u0 + 1) * 8);
        CP_ASYNC16(sb + SB_L(stage) + bsw0, g_pl + base + u0 * 8);
        CP_ASYNC16(sb + SB_L(stage) + bsw1, g_pl + base + (u0 + 1) * 8);
    };

    // ===== prologue: fill stage 0 =====
    issueA(0, 0);
    issueB(0, 0);
    CP_COMMIT();
    CP_WAIT_ALL();
    __syncthreads();

    // ===== mainloop =====
    for (int chunk = 0; chunk < 36; ++chunk) {
        const int cur = chunk & 1;
        const int nxt = cur ^ 1;
        const bool hasNext = (chunk + 1 < 36);
        if (hasNext) {
            issueA(nxt, chunk + 1);
            issueB(nxt, chunk + 1);
            CP_COMMIT();
        }

        const uint32_t aBase  = sb + SA(cur);
        const uint32_t bHBase = sb + SB_H(cur);
        const uint32_t bLBase = sb + SB_L(cur);

#pragma unroll
        for (int kk = 0; kk < 4; kk++) {
            uint32_t aH[2][4], bH[2][4], bL[2][4];
#pragma unroll
            for (int mt = 0; mt < 2; mt++) {
                int u = kk * 2 + laneSel;
                int off = mRowB[mt] + ((u ^ mRow7[mt]) & 7) * 16;
                ldmat_x4(aH[mt], aBase + off);
            }
#pragma unroll
            for (int nt2 = 0; nt2 < 2; nt2++) {
                int off = kk * 16 * 128 + bKRow + ((bUn[nt2] ^ bK7) & 7) * 16;
                ldmat_x4_t(bH[nt2], bHBase + off);
                ldmat_x4_t(bL[nt2], bLBase + off);
            }
#pragma unroll
            for (int mt = 0; mt < 2; mt++) {
#pragma unroll
                for (int nt = 0; nt < 4; nt++) {
                    int nt2 = nt >> 1, sub = (nt & 1) * 2;
                    mma16816h(acc[mt][nt], aH[mt], bH[nt2][sub], bH[nt2][sub + 1]);
                    mma16816h(acc[mt][nt], aH[mt], bL[nt2][sub], bL[nt2][sub + 1]);
                }
            }
        }

        CP_WAIT_ALL();
        __syncthreads();
    }

    // ===== epilogue: alpha, bias, scaled LeakyReLU =====
    const int rowInTile = lane >> 2;
    const int colInTile = (lane & 3) * 2;
#pragma unroll
    for (int mt = 0; mt < 2; mt++) {
        int o0 = mBase + mW + mt * 16 + rowInTile;
        int o1 = o0 + 8;
        float al0 = g_alpha[bat * 256 + o0], bi0 = cbias[o0];
        float al1 = g_alpha[bat * 256 + o1], bi1 = cbias[o1];
        float* p0 = out + (long)(bat * 256 + o0) * 4096 + nBase + nW + colInTile;
        float* p1 = out + (long)(bat * 256 + o1) * 4096 + nBase + nW + colInTile;
#pragma unroll
        for (int nt = 0; nt < 4; nt++) {
            float2 v0, v1;
            float v;
            v = acc[mt][nt][0] * al0 + bi0;
            v0.x = (v >= 0.f ? v : LRELU_SLOPE * v) * SQRT2F;
            v = acc[mt][nt][1] * al0 + bi0;
            v0.y = (v >= 0.f ? v : LRELU_SLOPE * v) * SQRT2F;
            v = acc[mt][nt][2] * al1 + bi1;
            v1.x = (v >= 0.f ? v : LRELU_SLOPE * v) * SQRT2F;
            v = acc[mt][nt][3] * al1 + bi1;
            v1.y = (v >= 0.f ? v : LRELU_SLOPE * v) * SQRT2F;
            *reinterpret_cast<float2*>(p0 + nt * 8) = v0;
            *reinterpret_cast<float2*>(p1 + nt * 8) = v1;
        }
    }
}

// ============================ launch ============================
extern "C" void kernel_launch(void* const* d_in, const int* in_sizes, int n_in,
                              void* d_out, int out_size) {
    const float* x       = (const float*)d_in[0];  // [8,256,128,128]
    const float* s       = (const float*)d_in[1];  // [8,512]
    const float* conv_w  = (const float*)d_in[2];  // [256,256,3,3]
    const float* conv_b  = (const float*)d_in[3];  // [256]
    const float* style_w = (const float*)d_in[4];  // [256,512]
    const float* style_b = (const float*)d_in[5];  // [256]
    const float* norm_g  = (const float*)d_in[6];  // [256]
    float* out = (float*)d_out;                    // [8,256,64,64]

    static int inited = 0;
    if (!inited) {
        cudaFuncSetAttribute(mma_conv_kernel,
                             cudaFuncAttributeMaxDynamicSharedMemorySize, CONV_SMEM);
        cudaFuncSetAttribute(blur_kernel,
                             cudaFuncAttributeMaxDynamicSharedMemorySize, BLUR_SMEM);
        inited = 1;
    }

    blur_kernel<<<4352, 256, BLUR_SMEM>>>(x, s, style_w, style_b);     // launch 1
    wsplit_kernel<<<dim3(256, 8), 256>>>(conv_w, norm_g);              // launch 2
    mma_conv_kernel<<<dim3(64, 2, 8), 256, CONV_SMEM>>>(conv_b, out);  // launch 3
}

// round 17
// speedup vs baseline: 1.9856x; 1.2650x over previous
#include <cuda_runtime.h>
#include <cuda_fp16.h>
#include <cstdint>

// ============================ helpers ============================
__device__ __forceinline__ uint32_t smem_to_u32(const void* smem_ptr) {
    uint32_t addr;
    asm("{ .reg .u64 tmp; cvta.to.shared.u64 tmp, %1; cvt.u32.u64 %0, tmp; }"
        : "=r"(addr) : "l"(smem_ptr));
    return addr;
}

#define CP_ASYNC16(dst, src) \
    asm volatile("cp.async.cg.shared.global [%0], [%1], 16;" \
                 :: "r"(dst), "l"(src) : "memory")
#define CP_COMMIT() asm volatile("cp.async.commit_group;" ::: "memory")
#define CP_WAIT_ALL() asm volatile("cp.async.wait_group 0;" ::: "memory")

__device__ __forceinline__ void ldmat_x4(uint32_t* r, uint32_t addr) {
    asm volatile("ldmatrix.sync.aligned.m8n8.x4.shared.b16 {%0,%1,%2,%3}, [%4];"
                 : "=r"(r[0]), "=r"(r[1]), "=r"(r[2]), "=r"(r[3]) : "r"(addr));
}
__device__ __forceinline__ void ldmat_x4_t(uint32_t* r, uint32_t addr) {
    asm volatile("ldmatrix.sync.aligned.m8n8.x4.trans.shared.b16 {%0,%1,%2,%3}, [%4];"
                 : "=r"(r[0]), "=r"(r[1]), "=r"(r[2]), "=r"(r[3]) : "r"(addr));
}
// fp16 inputs, fp32 accumulate
__device__ __forceinline__ void mma16816h(float* c, const uint32_t* a,
                                          uint32_t b0, uint32_t b1) {
    asm volatile(
        "mma.sync.aligned.m16n8k16.row.col.f32.f16.f16.f32 "
        "{%0,%1,%2,%3}, {%4,%5,%6,%7}, {%8,%9}, {%0,%1,%2,%3};"
        : "+f"(c[0]), "+f"(c[1]), "+f"(c[2]), "+f"(c[3])
        : "r"(a[0]), "r"(a[1]), "r"(a[2]), "r"(a[3]), "r"(b0), "r"(b1));
}

// ============================ scratch globals ============================
// Pre-shifted fp16 planes of the blurred input (single fp16 precision).
// Layout: [b][py][pvar][ic][row 0..64][col 0..63], row pitch 64 fp16 = 128B.
//   pvar 0: px=1, col c holds x(ix=2c-1); pvar 1: px=1, col c holds x(ix=2c+1);
//   pvar 2: px=0, col c holds x(ix=2c).
// Row 0 of py=1 planes (iy=-1 border) is read but NEVER written: stays zero
// from static initialization across all launches/replays.
#define PL_SIZE 4160  // 65*64
__device__ __half g_ph[8L * 2 * 3 * 256 * PL_SIZE];  // ~102 MB
__device__ float g_style[8 * 256];
__device__ float g_partial[4096];
__device__ float g_alpha[8 * 256];
// per-batch scaled weights (fp16), reordered k = t*256+ic
__device__ __align__(256) __half g_wA[8L * 256 * 2304];  // ~9.4 MB

#define LRELU_SLOPE 0.2f
#define SQRT2F 1.41421356237309515f

// ============================ K1: blur + split + style ============================
// blocks [0,4096): blur one half-plane (horizontal via lane shuffles, vertical
//   via one smem buffer), write fp16 parity-variant planes + sumsq partial.
// blocks [4096,4352): style[b,i] = s[b,:]@style_w[i,:] + style_b[i]
#define BLUR_SMEM ((68 * 128 + 8) * 4)   // 34.9 KB

__global__ __launch_bounds__(256) void blur_kernel(const float* __restrict__ x,
                                                   const float* __restrict__ s,
                                                   const float* __restrict__ style_w,
                                                   const float* __restrict__ style_b) {
    if (blockIdx.x >= 4096) {
        int wg = (blockIdx.x - 4096) * 8 + (threadIdx.x >> 5);  // b*256+i
        int lane = threadIdx.x & 31;
        int b = wg >> 8, i = wg & 255;
        const float* sp = s + b * 512;
        const float* wp = style_w + i * 512;
        float acc = 0.f;
#pragma unroll 4
        for (int j = lane; j < 512; j += 32) acc += sp[j] * wp[j];
#pragma unroll
        for (int o = 16; o; o >>= 1) acc += __shfl_xor_sync(0xffffffffu, acc, o);
        if (lane == 0) g_style[wg] = acc + style_b[i];
        return;
    }

    extern __shared__ __align__(16) float sm[];
    float* hb = sm;              // [68][128] horizontally-blurred rows
    float* red = hb + 68 * 128;

    const int bat = blockIdx.x >> 9;
    const int inBlk = blockIdx.x & 511;
    const int c = inBlk >> 1;
    const int plane = bat * 256 + c;
    const int h0 = (inBlk & 1) * 64;
    const int tid = threadIdx.x;
    const float* xp = x + (long)plane * 16384;

    // horizontal pass: direct global load + lane shuffles (c4 == lane)
    for (int pos = tid; pos < 68 * 32; pos += 256) {
        int r = pos >> 5, c4 = pos & 31;
        int h = h0 - 2 + r;
        float4 v = make_float4(0.f, 0.f, 0.f, 0.f);
        if ((unsigned)h < 128u)
            v = *reinterpret_cast<const float4*>(xp + h * 128 + c4 * 4);
        float lz = __shfl_up_sync(0xffffffffu, v.z, 1);
        float lw = __shfl_up_sync(0xffffffffu, v.w, 1);
        float rx = __shfl_down_sync(0xffffffffu, v.x, 1);
        float ry = __shfl_down_sync(0xffffffffu, v.y, 1);
        if (c4 == 0)  { lz = 0.f; lw = 0.f; }
        if (c4 == 31) { rx = 0.f; ry = 0.f; }
        float4 o;
        o.x = lz + 4.f * lw + 6.f * v.x + 4.f * v.y + v.z;
        o.y = lw + 4.f * v.x + 6.f * v.y + 4.f * v.z + v.w;
        o.z = v.x + 4.f * v.y + 6.f * v.z + 4.f * v.w + rx;
        o.w = v.y + 4.f * v.z + 6.f * v.w + 4.f * rx + ry;
        *reinterpret_cast<float4*>(hb + r * 128 + c4 * 4) = o;
    }
    __syncthreads();

    // vertical pass + fp16 convert + parity-variant writes + sumsq
    float ss = 0.f;
    for (int pos = tid; pos < 64 * 32; pos += 256) {
        int r = pos >> 5, c4 = pos & 31;  // c4 == lane
        const float* col = hb + r * 128 + c4 * 4;
        float4 h0v = *reinterpret_cast<const float4*>(col);
        float4 h1v = *reinterpret_cast<const float4*>(col + 128);
        float4 h2v = *reinterpret_cast<const float4*>(col + 256);
        float4 h3v = *reinterpret_cast<const float4*>(col + 384);
        float4 h4v = *reinterpret_cast<const float4*>(col + 512);
        // v0..v3 at ix = 4*c4 + {0,1,2,3}, iy = h0 + r
        float v0 = (h0v.x + 4.f * h1v.x + 6.f * h2v.x + 4.f * h3v.x + h4v.x) * (1.f / 256.f);
        float v1 = (h0v.y + 4.f * h1v.y + 6.f * h2v.y + 4.f * h3v.y + h4v.y) * (1.f / 256.f);
        float v2 = (h0v.z + 4.f * h1v.z + 6.f * h2v.z + 4.f * h3v.z + h4v.z) * (1.f / 256.f);
        float v3 = (h0v.w + 4.f * h1v.w + 6.f * h2v.w + 4.f * h3v.w + h4v.w) * (1.f / 256.f);
        ss += v0 * v0 + v1 * v1 + v2 * v2 + v3 * v3;

        unsigned short hh[4];
        hh[0] = __half_as_ushort(__float2half(v0));
        hh[1] = __half_as_ushort(__float2half(v1));
        hh[2] = __half_as_ushort(__float2half(v2));
        hh[3] = __half_as_ushort(__float2half(v3));
        // neighbor v3 (ix = 4c4-1) for the pvar0 packed write
        unsigned ph3 = __shfl_up_sync(0xffffffffu, (unsigned)hh[3], 1);
        if (c4 == 0) ph3 = 0u;  // x(-1) = 0 border

        int iy = h0 + r;
        int py = iy & 1;
        int prow = (iy >> 1) + 1;
        long rowOff = (long)prow * 64;
        long p0b = ((long)((bat * 2 + py) * 3 + 0) * 256 + c) * PL_SIZE + rowOff;
        long p1b = ((long)((bat * 2 + py) * 3 + 1) * 256 + c) * PL_SIZE + rowOff;
        long p2b = ((long)((bat * 2 + py) * 3 + 2) * 256 + c) * PL_SIZE + rowOff;
        int col2 = 2 * c4;

        // pvar2 (px=0): (v0, v2)
        *reinterpret_cast<unsigned*>(&g_ph[p2b + col2]) = (unsigned)hh[0] | ((unsigned)hh[2] << 16);
        // pvar1 (x(2c+1)): (v1, v3)
        *reinterpret_cast<unsigned*>(&g_ph[p1b + col2]) = (unsigned)hh[1] | ((unsigned)hh[3] << 16);
        // pvar0 (x(2c-1)): (prev v3, v1)
        *reinterpret_cast<unsigned*>(&g_ph[p0b + col2]) = ph3 | ((unsigned)hh[1] << 16);
    }
#pragma unroll
    for (int o = 16; o; o >>= 1) ss += __shfl_xor_sync(0xffffffffu, ss, o);
    if ((tid & 31) == 0) red[tid >> 5] = ss;
    __syncthreads();
    if (tid == 0) {
        float t = 0.f;
#pragma unroll
        for (int k = 0; k < 8; k++) t += red[k];
        g_partial[bat * 512 + inBlk] = t;
    }
}

// ============================ K2: wsplit + rscale + alpha ============================
__global__ __launch_bounds__(256) void wsplit_kernel(const float* __restrict__ w,
                                                     const float* __restrict__ norm_g) {
    __shared__ float ws[2304];
    __shared__ float rs[256];
    __shared__ float red[8];
    const int o = blockIdx.x;
    const int bat = blockIdx.y;
    const int tid = threadIdx.x;

    const float4* wsrc = reinterpret_cast<const float4*>(w + (long)o * 2304);
    for (int i = tid; i < 576; i += 256)
        *reinterpret_cast<float4*>(ws + i * 4) = wsrc[i];

    {
        int p = bat * 256 + tid;
        float ssum = g_partial[2 * p] + g_partial[2 * p + 1];
        float ms = ssum * (1.f / 16384.f);
        rs[tid] = rsqrtf(ms + 1e-8f) * norm_g[tid] * g_style[p];
    }
    __syncthreads();

    {
        float sv = g_style[bat * 256 + tid];
        float wq = 0.f;
#pragma unroll
        for (int t = 0; t < 9; t++) { float v = ws[tid * 9 + t]; wq += v * v; }
        float pa = sv * sv * wq;
#pragma unroll
        for (int off = 16; off; off >>= 1) pa += __shfl_xor_sync(0xffffffffu, pa, off);
        if ((tid & 31) == 0) red[tid >> 5] = pa;
    }

    {
        const float rsc = rs[tid];
        long dstBase = (long)(bat * 256 + o) * 2304 + tid;
#pragma unroll
        for (int t = 0; t < 9; t++)
            g_wA[dstBase + t * 256] = __float2half(ws[tid * 9 + t] * rsc);
    }

    __syncthreads();
    if (tid == 0) {
        float acc = 0.f;
#pragma unroll
        for (int k = 0; k < 8; k++) acc += red[k];
        const float sc = 1.f / 48.f;  // 1/sqrt(256*9)
        g_alpha[bat * 256 + o] = sc * rsqrtf(sc * sc * acc + 1e-8f);
    }
}

// ============================ K3: HMMA conv GEMM ============================
// CTA tile: M=128 (o), N=64 (one output row). grid (64,2,8).
// K = 2304 = 36 chunks of 64. Plain fp16 (A and B): C = Ah*Bh (~3e-4 rel err).
// ALL staging via cp.async.cg 16B. smem: A 16KB + B 8KB per stage,
// double-buffered = 48KB. launch_bounds(256,2): no spills.

#define SA(st) ((st) * 16384)
#define SB(st) (32768 + (st) * 8192)
#define CONV_SMEM 49152

__global__ __launch_bounds__(256, 2)
void mma_conv_kernel(const float* __restrict__ cbias, float* __restrict__ out) {
    extern __shared__ __align__(1024) char smem[];
    const uint32_t sb = smem_to_u32(smem);
    const int tid = threadIdx.x;
    const int lane = tid & 31;
    const int wid = tid >> 5;
    const int warpM = wid >> 1;         // 0..3 (32 rows each)
    const int warpN = wid & 1;          // 0..1 (32 cols each)
    const int bat = blockIdx.z;
    const int mBase = blockIdx.y * 128;
    const int oy = blockIdx.x;          // output row
    const int nBase = blockIdx.x * 64;

    // ---- A staging: 8 lanes per 128B row-line, 4 rows per thread ----
    const int aj = tid & 7;
    const int ar0 = tid >> 3;           // 0..31

    // ---- B staging: 4 threads per ic-row, 2 units each ----
    const int icB = tid >> 2;           // 0..63
    const int u0 = (tid & 3) * 2;       // 0,2,4,6
    const int bsw0 = icB * 128 + (((u0    ) ^ (icB & 7)) & 7) * 16;
    const int bsw1 = icB * 128 + (((u0 + 1) ^ (icB & 7)) & 7) * 16;

    // ---- fragment constants ----
    const int laneRow = lane & 15;
    const int laneSel = lane >> 4;
    const int mW = warpM * 32;
    const int nW = warpN * 32;
    int mRowB[2], mRow7[2];
#pragma unroll
    for (int mt = 0; mt < 2; mt++) {
        int m = mW + mt * 16 + laneRow;
        mRowB[mt] = m * 128;
        mRow7[mt] = m & 7;
    }
    const int bKRow = laneRow * 128;
    const int bK7 = laneRow & 7;
    int bUn[2];
#pragma unroll
    for (int nt2 = 0; nt2 < 2; nt2++)
        bUn[nt2] = warpN * 4 + nt2 * 2 + laneSel;   // 0..7

    float acc[2][4][4];
#pragma unroll
    for (int i = 0; i < 2; i++)
#pragma unroll
        for (int j = 0; j < 4; j++)
#pragma unroll
            for (int k = 0; k < 4; k++) acc[i][j][k] = 0.f;

    auto issueA = [&](int stage, int chunk) {
#pragma unroll
        for (int p = 0; p < 4; p++) {
            int r = ar0 + 32 * p;
            long src = (long)(bat * 256 + mBase + r) * 2304 + chunk * 64 + aj * 8;
            int sw = r * 128 + ((aj ^ (r & 7)) & 7) * 16;
            CP_ASYNC16(sb + SA(stage) + sw, g_wA + src);
        }
    };
    auto issueB = [&](int stage, int chunk) {
        int tap = chunk >> 2;
        int icq = chunk & 3;
        int ty = (tap >= 6) ? 2 : (tap >= 3 ? 1 : 0);
        int tx = tap - ty * 3;
        int py = (ty == 1) ? 0 : 1;
        int pvar = (tx == 0) ? 0 : (tx == 2 ? 1 : 2);
        int row = oy + (ty != 0);
        long base = ((long)((bat * 2 + py) * 3 + pvar) * 256 + icq * 64 + icB)
                    * (long)PL_SIZE + (long)row * 64;
        CP_ASYNC16(sb + SB(stage) + bsw0, g_ph + base + u0 * 8);
        CP_ASYNC16(sb + SB(stage) + bsw1, g_ph + base + (u0 + 1) * 8);
    };

    // ===== prologue: fill stage 0 =====
    issueA(0, 0);
    issueB(0, 0);
    CP_COMMIT();
    CP_WAIT_ALL();
    __syncthreads();

    // ===== mainloop =====
    for (int chunk = 0; chunk < 36; ++chunk) {
        const int cur = chunk & 1;
        const int nxt = cur ^ 1;
        const bool hasNext = (chunk + 1 < 36);
        if (hasNext) {
            issueA(nxt, chunk + 1);
            issueB(nxt, chunk + 1);
            CP_COMMIT();
        }

        const uint32_t aBase = sb + SA(cur);
        const uint32_t bBase = sb + SB(cur);

#pragma unroll
        for (int kk = 0; kk < 4; kk++) {
            uint32_t aH[2][4], bH[2][4];
#pragma unroll
            for (int mt = 0; mt < 2; mt++) {
                int u = kk * 2 + laneSel;
                int off = mRowB[mt] + ((u ^ mRow7[mt]) & 7) * 16;
                ldmat_x4(aH[mt], aBase + off);
            }
#pragma unroll
            for (int nt2 = 0; nt2 < 2; nt2++) {
                int off = kk * 16 * 128 + bKRow + ((bUn[nt2] ^ bK7) & 7) * 16;
                ldmat_x4_t(bH[nt2], bBase + off);
            }
#pragma unroll
            for (int mt = 0; mt < 2; mt++) {
#pragma unroll
                for (int nt = 0; nt < 4; nt++) {
                    int nt2 = nt >> 1, sub = (nt & 1) * 2;
                    mma16816h(acc[mt][nt], aH[mt], bH[nt2][sub], bH[nt2][sub + 1]);
                }
            }
        }

        CP_WAIT_ALL();
        __syncthreads();
    }

    // ===== epilogue: alpha, bias, scaled LeakyReLU =====
    const int rowInTile = lane >> 2;
    const int colInTile = (lane & 3) * 2;
#pragma unroll
    for (int mt = 0; mt < 2; mt++) {
        int o0 = mBase + mW + mt * 16 + rowInTile;
        int o1 = o0 + 8;
        float al0 = g_alpha[bat * 256 + o0], bi0 = cbias[o0];
        float al1 = g_alpha[bat * 256 + o1], bi1 = cbias[o1];
        float* p0 = out + (long)(bat * 256 + o0) * 4096 + nBase + nW + colInTile;
        float* p1 = out + (long)(bat * 256 + o1) * 4096 + nBase + nW + colInTile;
#pragma unroll
        for (int nt = 0; nt < 4; nt++) {
            float2 v0, v1;
            float v;
            v = acc[mt][nt][0] * al0 + bi0;
            v0.x = (v >= 0.f ? v : LRELU_SLOPE * v) * SQRT2F;
            v = acc[mt][nt][1] * al0 + bi0;
            v0.y = (v >= 0.f ? v : LRELU_SLOPE * v) * SQRT2F;
            v = acc[mt][nt][2] * al1 + bi1;
            v1.x = (v >= 0.f ? v : LRELU_SLOPE * v) * SQRT2F;
            v = acc[mt][nt][3] * al1 + bi1;
            v1.y = (v >= 0.f ? v : LRELU_SLOPE * v) * SQRT2F;
            *reinterpret_cast<float2*>(p0 + nt * 8) = v0;
            *reinterpret_cast<float2*>(p1 + nt * 8) = v1;
        }
    }
}

// ============================ launch ============================
extern "C" void kernel_launch(void* const* d_in, const int* in_sizes, int n_in,
                              void* d_out, int out_size) {
    const float* x       = (const float*)d_in[0];  // [8,256,128,128]
    const float* s       = (const float*)d_in[1];  // [8,512]
    const float* conv_w  = (const float*)d_in[2];  // [256,256,3,3]
    const float* conv_b  = (const float*)d_in[3];  // [256]
    const float* style_w = (const float*)d_in[4];  // [256,512]
    const float* style_b = (const float*)d_in[5];  // [256]
    const float* norm_g  = (const float*)d_in[6];  // [256]
    float* out = (float*)d_out;                    // [8,256,64,64]

    static int inited = 0;
    if (!inited) {
        cudaFuncSetAttribute(mma_conv_kernel,
                             cudaFuncAttributeMaxDynamicSharedMemorySize, CONV_SMEM);
        cudaFuncSetAttribute(blur_kernel,
                             cudaFuncAttributeMaxDynamicSharedMemorySize, BLUR_SMEM);
        inited = 1;
    }

    blur_kernel<<<4352, 256, BLUR_SMEM>>>(x, s, style_w, style_b);     // launch 1
    wsplit_kernel<<<dim3(256, 8), 256>>>(conv_w, norm_g);              // launch 2
    mma_conv_kernel<<<dim3(64, 2, 8), 256, CONV_SMEM>>>(conv_b, out);  // launch 3
}